// round 10
// baseline (speedup 1.0000x reference)
#include <cuda_runtime.h>
#include <cstdint>

#define BATCH 1024
#define TT    20
#define HH    768
#define G4    3072   // 4*H
#define DIN   4
#define HB    (HH * BATCH)

#define NB  148
#define NTC 256      // compute threads (warps 0-7)
#define NTP 256      // prep threads (warps 8-15)
#define NT  (NTC + NTP)
#define CPT 21

// ---------------- scratch (static __device__, no allocs) ----------------
__device__ float  g_evsumtot[32];
__device__ float  g_hsumtot[32];
__device__ float2 g_rb[TT * G4];            // (rowsum, bih+bhh) per row
__device__ float  g_gatesT[3 * HB];         // step-0 gates, TRANSPOSED [gate(i,g,o)][h][b]
__device__ unsigned g_bar_count;
__device__ unsigned g_prep_cnt[32];         // per-step prep completion (target 8*NB)

__constant__ int c_g3row[3] = {0, 2, 3};    // live gates at t=0 (f dead: c0=0)

// ---------------- activations: HW tanh (MUFU.TANH) ----------------
__device__ __forceinline__ float htanh(float x) {
    float r; asm("tanh.approx.f32 %0, %1;" : "=f"(r) : "f"(x)); return r;
}
__device__ __forceinline__ float fsig(float x) {
    return fmaf(0.5f, htanh(0.5f * x), 0.5f);
}
__device__ __forceinline__ uint32_t to_tf32_bits(float x) {
    float r; asm("cvt.rna.tf32.f32 %0, %1;" : "=f"(r) : "f"(x));
    return __float_as_uint(r);
}
__device__ __forceinline__ float dot4(float4 x, float4 w) {
    return fmaf(x.x, w.x, fmaf(x.y, w.y, fmaf(x.z, w.z, x.w * w.w)));
}
#define BARC() asm volatile("bar.sync 1, %0;" :: "n"(NTC) : "memory")

// warp row-sum of 768 floats; result on lane 0
__device__ __forceinline__ float sum768(const float* __restrict__ p, int lane) {
    float4 a0 = *(const float4*)(p + 0 * 128 + lane * 4);
    float4 a1 = *(const float4*)(p + 1 * 128 + lane * 4);
    float4 a2 = *(const float4*)(p + 2 * 128 + lane * 4);
    float4 a3 = *(const float4*)(p + 3 * 128 + lane * 4);
    float4 a4 = *(const float4*)(p + 4 * 128 + lane * 4);
    float4 a5 = *(const float4*)(p + 5 * 128 + lane * 4);
    float s = ((a0.x + a0.y) + (a0.z + a0.w)) + ((a1.x + a1.y) + (a1.z + a1.w))
            + ((a2.x + a2.y) + (a2.z + a2.w)) + ((a3.x + a3.y) + (a3.z + a3.w))
            + ((a4.x + a4.y) + (a4.z + a4.w)) + ((a5.x + a5.y) + (a5.z + a5.w));
    #pragma unroll
    for (int o = 16; o; o >>= 1) s += __shfl_down_sync(0xffffffffu, s, o);
    return s;
}

// two row-sums with ALL 12 loads issued before any reduction (MLP 12)
__device__ __forceinline__ void sum768x2(const float* __restrict__ p0,
                                         const float* __restrict__ p1,
                                         int lane, float& s0out, float& s1out) {
    float4 a0 = *(const float4*)(p0 + 0 * 128 + lane * 4);
    float4 a1 = *(const float4*)(p0 + 1 * 128 + lane * 4);
    float4 a2 = *(const float4*)(p0 + 2 * 128 + lane * 4);
    float4 a3 = *(const float4*)(p0 + 3 * 128 + lane * 4);
    float4 a4 = *(const float4*)(p0 + 4 * 128 + lane * 4);
    float4 a5 = *(const float4*)(p0 + 5 * 128 + lane * 4);
    float4 b0 = *(const float4*)(p1 + 0 * 128 + lane * 4);
    float4 b1 = *(const float4*)(p1 + 1 * 128 + lane * 4);
    float4 b2 = *(const float4*)(p1 + 2 * 128 + lane * 4);
    float4 b3 = *(const float4*)(p1 + 3 * 128 + lane * 4);
    float4 b4 = *(const float4*)(p1 + 4 * 128 + lane * 4);
    float4 b5 = *(const float4*)(p1 + 5 * 128 + lane * 4);
    float s0 = ((a0.x + a0.y) + (a0.z + a0.w)) + ((a1.x + a1.y) + (a1.z + a1.w))
             + ((a2.x + a2.y) + (a2.z + a2.w)) + ((a3.x + a3.y) + (a3.z + a3.w))
             + ((a4.x + a4.y) + (a4.z + a4.w)) + ((a5.x + a5.y) + (a5.z + a5.w));
    float s1 = ((b0.x + b0.y) + (b0.z + b0.w)) + ((b1.x + b1.y) + (b1.z + b1.w))
             + ((b2.x + b2.y) + (b2.z + b2.w)) + ((b3.x + b3.y) + (b3.z + b3.w))
             + ((b4.x + b4.y) + (b4.z + b4.w)) + ((b5.x + b5.y) + (b5.z + b5.w));
    #pragma unroll
    for (int o = 16; o; o >>= 1) {
        s0 += __shfl_down_sync(0xffffffffu, s0, o);
        s1 += __shfl_down_sync(0xffffffffu, s1, o);
    }
    s0out = s0; s1out = s1;
}

// ---------------- init ----------------
__global__ void init_kernel(const float* __restrict__ fcb, float* __restrict__ out) {
    int t = blockIdx.x * blockDim.x + threadIdx.x;
    if (t < BATCH) out[t] = fcb[0];
    if (t < 32) { g_evsumtot[t] = 0.f; g_hsumtot[t] = 0.f; g_prep_cnt[t] = 0u; }
    if (t == 32) g_bar_count = 0;
}

// ---------------- front kernel: gemm0 (blocks 0..287) + prep step 1 (blocks 288..799) ----------------
#define BM 128
#define BN 64
#define BK 32
#define APAD 4
#define ASTR (BK + APAD)
#define NCH (HH / BK)
#define FB_GEMM 288
#define FB_TOTAL (FB_GEMM + 512)

__device__ __forceinline__ void mma_tf32(float* d, const uint32_t* a, const uint32_t* b) {
    asm volatile(
        "mma.sync.aligned.m16n8k8.row.col.f32.tf32.tf32.f32 "
        "{%0,%1,%2,%3}, {%4,%5,%6,%7}, {%8,%9}, {%0,%1,%2,%3};"
        : "+f"(d[0]), "+f"(d[1]), "+f"(d[2]), "+f"(d[3])
        : "r"(a[0]), "r"(a[1]), "r"(a[2]), "r"(a[3]), "r"(b[0]), "r"(b[1]));
}

__global__ __launch_bounds__(256) void front_kernel(
    const float* __restrict__ ev, const float* __restrict__ whh,
    const float* __restrict__ bih, const float* __restrict__ bhh) {
    __shared__ float As[BM * ASTR];
    __shared__ float Bs[BN * ASTR];
    const int blk = blockIdx.x;
    const int tid = threadIdx.x;
    const int wid = tid >> 5, lane = tid & 31;

    if (blk >= FB_GEMM) {
        // ---- prep for step 1 (high-parallelism sweep) ----
        const int w = (blk - FB_GEMM) * 8 + wid;      // 0..4095
        if (w < G4) {
            const int row = G4 + w;                    // t = 1 rows
            float s = sum768(whh + (size_t)row * HH, lane);
            if (lane == 0) g_rb[row] = make_float2(s, bih[row] + bhh[row]);
        } else {
            const int bb = w - G4;                     // 0..1023
            float s = sum768(ev + ((size_t)bb * TT + 1) * HH, lane);
            if (lane == 0) atomicAdd(&g_evsumtot[1], s);   // RED
        }
        return;
    }

    // ---- GEMM tile: 128(M batch) x 64(N) ----
    const int grp  = lane >> 2, tig = lane & 3;
    const int bx   = blk % 36, by = blk / 36;
    const int gidx = bx / 12;
    const int gate = c_g3row[gidx];
    const int hn   = (bx % 12) * BN;
    const int bm   = by * BM;
    const int wm   = (wid >> 1) * 32;     // 0..96
    const int wn   = (wid & 1) * 32;      // 0,32
    const size_t evStride = (size_t)TT * HH;

    float acc[2][4][4];
    #pragma unroll
    for (int i = 0; i < 2; i++)
        #pragma unroll
        for (int j = 0; j < 4; j++)
            #pragma unroll
            for (int r = 0; r < 4; r++) acc[i][j][r] = 0.f;

    float4 ra[6];
    #pragma unroll
    for (int i = 0; i < 6; i++) {
        const int lin = tid + i * 256;
        const int r = lin >> 3, q = (lin & 7) * 4;
        ra[i] = (r < BM)
            ? *(const float4*)(ev + (size_t)(bm + r) * evStride + q)
            : *(const float4*)(whh + (size_t)(gate * HH + hn + (r - BM)) * HH + q);
    }

    for (int chunk = 0; chunk < NCH; chunk++) {
        #pragma unroll
        for (int i = 0; i < 6; i++) {
            const int lin = tid + i * 256;
            const int r = lin >> 3, q = (lin & 7) * 4;
            uint4 t4; t4.x = to_tf32_bits(ra[i].x); t4.y = to_tf32_bits(ra[i].y);
                      t4.z = to_tf32_bits(ra[i].z); t4.w = to_tf32_bits(ra[i].w);
            if (r < BM) *(uint4*)(As + r * ASTR + q) = t4;
            else        *(uint4*)(Bs + (r - BM) * ASTR + q) = t4;
        }
        __syncthreads();
        if (chunk + 1 < NCH) {
            const int k0 = (chunk + 1) * BK;
            #pragma unroll
            for (int i = 0; i < 6; i++) {
                const int lin = tid + i * 256;
                const int r = lin >> 3, q = (lin & 7) * 4;
                ra[i] = (r < BM)
                    ? *(const float4*)(ev + (size_t)(bm + r) * evStride + k0 + q)
                    : *(const float4*)(whh + (size_t)(gate * HH + hn + (r - BM)) * HH + k0 + q);
            }
        }
        #pragma unroll
        for (int kk = 0; kk < 4; kk++) {
            const int k8 = kk * 8;
            uint32_t af[2][4];
            #pragma unroll
            for (int mi = 0; mi < 2; mi++) {
                const float* ar = As + (wm + mi * 16) * ASTR + k8;
                af[mi][0] = __float_as_uint(ar[grp * ASTR + tig]);
                af[mi][1] = __float_as_uint(ar[(grp + 8) * ASTR + tig]);
                af[mi][2] = __float_as_uint(ar[grp * ASTR + tig + 4]);
                af[mi][3] = __float_as_uint(ar[(grp + 8) * ASTR + tig + 4]);
            }
            #pragma unroll
            for (int ni = 0; ni < 4; ni++) {
                const float* br = Bs + (wn + ni * 8 + grp) * ASTR + k8;
                uint32_t bf[2];
                bf[0] = __float_as_uint(br[tig]);
                bf[1] = __float_as_uint(br[tig + 4]);
                #pragma unroll
                for (int mi = 0; mi < 2; mi++)
                    mma_tf32(acc[mi][ni], af[mi], bf);
            }
        }
        __syncthreads();
    }

    float* gT = g_gatesT + (size_t)gidx * HB;
    #pragma unroll
    for (int mi = 0; mi < 2; mi++) {
        const int m0 = bm + wm + mi * 16 + grp;
        #pragma unroll
        for (int ni = 0; ni < 4; ni++) {
            const int h0 = hn + wn + ni * 8 + 2 * tig;
            gT[(size_t)h0 * BATCH + m0]           = acc[mi][ni][0];
            gT[(size_t)(h0 + 1) * BATCH + m0]     = acc[mi][ni][1];
            gT[(size_t)h0 * BATCH + m0 + 8]       = acc[mi][ni][2];
            gT[(size_t)(h0 + 1) * BATCH + m0 + 8] = acc[mi][ni][3];
        }
    }
}

// ---------------- persistent sequential kernel: windows 0..19 + fc ----------------
__global__ __launch_bounds__(NT, 1) void seq_kernel(
    const float* __restrict__ price, const float* __restrict__ ev,
    const float* __restrict__ whh,   const float* __restrict__ wih,
    const float* __restrict__ bih,   const float* __restrict__ bhh,
    const float* __restrict__ fcw,   float* __restrict__ out) {
    __shared__ float4 s_w[2][4 * CPT];
    __shared__ float  s_gc[4 * CPT];
    __shared__ float  s_red[8];
    __shared__ float  s_hx;
    __shared__ float  s_fcw[CPT];

    const int blk = blockIdx.x;
    const int tix = threadIdx.x;
    const int lane = tix & 31, wrp = tix >> 5;
    const int t0  = blk >> 2;                    // uniform per block (0..36)

    if (tix < NTC) {
        // =========================== COMPUTE WARPS (0-7) ===========================
        const int b = ((blk << 8) + tix) & 1023;     // constant per thread
        float c[CPT];
        float2 rbreg = make_float2(0.f, 0.f);
        float4 wreg  = make_float4(0.f, 0.f, 0.f, 0.f);

        // ---- window 0: cells t=0 from gemm gates ----
        if (tix < 3 * CPT) {
            const int g = tix / CPT, k = tix - g * CPT;
            const int h = t0 + 37 * k;
            if (h < HH) {
                const int row = c_g3row[g] * HH + h;
                s_gc[tix]  = bih[row] + bhh[row];
                s_w[0][tix] = *(const float4*)(wih + (size_t)row * DIN);
            }
        }
        BARC();
        if (tix < 4 * CPT) {                         // prefetch step-1 consts (sealed by front)
            const int g = tix / CPT, k = tix - g * CPT;
            const int h = t0 + 37 * k;
            if (h < HH) {
                const int row = G4 + g * HH + h;
                rbreg = g_rb[row];
                wreg  = *(const float4*)(wih + (size_t)row * DIN);
            }
        }
        {
            float4 x = *(const float4*)(price + (size_t)b * TT * DIN);
            float hloc = 0.f;
            #pragma unroll
            for (int k = 0; k < CPT; k++) {
                const int h = t0 + 37 * k;
                if (h < HH) {
                    const size_t base = ((size_t)h << 10) + b;
                    float gi = g_gatesT[base]          + dot4(x, s_w[0][k])           + s_gc[k];
                    float gg = g_gatesT[HB + base]     + dot4(x, s_w[0][CPT + k])     + s_gc[CPT + k];
                    float go = g_gatesT[2 * HB + base] + dot4(x, s_w[0][2 * CPT + k]) + s_gc[2 * CPT + k];
                    float cv = fsig(gi) * htanh(gg);
                    c[k] = cv;
                    hloc += fsig(go) * htanh(cv);
                } else c[k] = 0.f;
            }
            if (tix < 4 * CPT) s_w[1][tix] = wreg;
            #pragma unroll
            for (int o = 16; o; o >>= 1) hloc += __shfl_down_sync(0xffffffffu, hloc, o);
            if (lane == 0) s_red[wrp] = hloc;
        }
        BARC();                                       // W0
        if (tix == 0) {
            float v = 0.f;
            #pragma unroll
            for (int q = 0; q < 8; q++) v += s_red[q];
            atomicAdd(&g_hsumtot[0], v);              // RED
            __threadfence();
            atomicAdd(&g_bar_count, 1u);              // RED arrival
        }

        // ---- windows t = 1..19 ----
        for (int t = 1; t < TT; t++) {
            const int cur = t & 1;
            if (tix == 0) {
                volatile unsigned* vc = &g_bar_count;
                const unsigned tgt = (unsigned)t * NB;
                while (*vc < tgt) { }
                if (t < TT - 1) {                     // prep(t+1) must be sealed for prefetch
                    volatile unsigned* vp = &g_prep_cnt[t + 1];
                    while (*vp < 8u * NB) { }
                }
                s_hx = ((volatile float*)g_hsumtot)[t - 1]
                     + ((volatile float*)g_evsumtot)[t];
            }
            BARC();
            if (tix < 4 * CPT) s_gc[tix] = fmaf(s_hx, rbreg.x, rbreg.y);
            BARC();
            // prefetch step t+1 consts (guarded by prep counter poll above)
            if (t < TT - 1 && tix < 4 * CPT) {
                const int g = tix / CPT, k = tix - g * CPT;
                const int h = t0 + 37 * k;
                if (h < HH) {
                    const int row = (t + 1) * G4 + g * HH + h;
                    rbreg = g_rb[row];
                    wreg  = *(const float4*)(wih + (size_t)row * DIN);
                }
            }
            if (t == TT - 2 && tix >= 4 * CPT && tix < 5 * CPT) {
                const int k = tix - 4 * CPT;
                const int h = t0 + 37 * k;
                s_fcw[k] = (h < HH) ? fcw[h] : 0.f;
            }

            float4 x = *(const float4*)(price + ((size_t)b * TT + t) * DIN);
            float hloc = 0.f, floc = 0.f;
            #pragma unroll
            for (int k = 0; k < CPT; k++) {
                const int h = t0 + 37 * k;
                if (h < HH) {
                    float gi = dot4(x, s_w[cur][k])           + s_gc[k];
                    float gf = dot4(x, s_w[cur][CPT + k])     + s_gc[CPT + k];
                    float gg = dot4(x, s_w[cur][2 * CPT + k]) + s_gc[2 * CPT + k];
                    float go = dot4(x, s_w[cur][3 * CPT + k]) + s_gc[3 * CPT + k];
                    float ct = fsig(gf) * c[k] + fsig(gi) * htanh(gg);
                    c[k] = ct;
                    float hv = fsig(go) * htanh(ct);
                    if (t == TT - 1) floc = fmaf(hv, s_fcw[k], floc);
                    else             hloc += hv;
                }
            }
            if (t < TT - 1 && tix < 4 * CPT) s_w[cur ^ 1][tix] = wreg;

            if (t == TT - 1) {
                atomicAdd(&out[b], floc);             // RED, 37 per address
            } else {
                #pragma unroll
                for (int o = 16; o; o >>= 1) hloc += __shfl_down_sync(0xffffffffu, hloc, o);
                if (lane == 0) s_red[wrp] = hloc;
                BARC();                               // W(t)
                if (tix == 0) {
                    float v = 0.f;
                    #pragma unroll
                    for (int q = 0; q < 8; q++) v += s_red[q];
                    atomicAdd(&g_hsumtot[t], v);      // RED
                    __threadfence();
                    atomicAdd(&g_bar_count, 1u);      // RED arrival
                }
            }
        }
    } else {
        // ================= PREP WARPS (8-15): FREE-RUNNING STREAM =================
        const int ptix = tix - NTC;
        const int pw = ptix >> 5, plane = ptix & 31;
        for (int tp = 2; tp < TT; tp++) {
            // round 1: rows j = pw and pw+8 (always valid)
            {
                const int r0 = blk + 148 * pw;
                const int r1 = blk + 148 * (pw + 8);
                const int row0 = tp * G4 + r0, row1 = tp * G4 + r1;
                float s0, s1;
                sum768x2(whh + (size_t)row0 * HH, whh + (size_t)row1 * HH, plane, s0, s1);
                if (plane == 0) {
                    g_rb[row0] = make_float2(s0, bih[row0] + bhh[row0]);
                    g_rb[row1] = make_float2(s1, bih[row1] + bhh[row1]);
                }
            }
            // round 2: row j = pw+16 (maybe) + ev batch blk*7+pw (maybe)
            {
                const int j2 = pw + 16;
                const int r2 = blk + 148 * j2;
                const bool v2 = (j2 < 21) && (r2 < G4);
                const int bb = blk * 7 + pw;
                const bool ve = (pw < 7) && (bb < BATCH);
                const int row2 = tp * G4 + (v2 ? r2 : 0);
                const float* p2 = whh + (size_t)row2 * HH;
                const float* pe = ve ? (ev + ((size_t)bb * TT + tp) * HH) : (ev);
                float s2, se;
                sum768x2(p2, pe, plane, s2, se);
                if (plane == 0) {
                    if (v2) g_rb[row2] = make_float2(s2, bih[row2] + bhh[row2]);
                    if (ve) atomicAdd(&g_evsumtot[tp], se);   // RED
                }
            }
            if (plane == 0) {
                __threadfence();
                atomicAdd(&g_prep_cnt[tp], 1u);               // RED completion
            }
        }
    }
}

// ---------------- launch ----------------
extern "C" void kernel_launch(void* const* d_in, const int* in_sizes, int n_in,
                              void* d_out, int out_size) {
    const float* price = (const float*)d_in[0];   // (B,T,4)
    const float* ev    = (const float*)d_in[1];   // (B,T,H)
    const float* wih   = (const float*)d_in[2];   // (T,4H,4)
    const float* whh   = (const float*)d_in[3];   // (T,4H,H)
    const float* bih   = (const float*)d_in[4];   // (T,4H)
    const float* bhh   = (const float*)d_in[5];   // (T,4H)
    const float* fcw   = (const float*)d_in[6];   // (1,H)
    const float* fcb   = (const float*)d_in[7];   // (1,)
    float* out = (float*)d_out;                    // (B,1)
    (void)in_sizes; (void)n_in; (void)out_size;

    init_kernel<<<4, 256>>>(fcb, out);
    front_kernel<<<FB_TOTAL, 256>>>(ev, whh, bih, bhh);
    seq_kernel<<<NB, NT>>>(price, ev, whh, wih, bih, bhh, fcw, out);
}

// round 12
// speedup vs baseline: 1.0872x; 1.0872x over previous
#include <cuda_runtime.h>
#include <cstdint>

#define BATCH 1024
#define TT    20
#define HH    768
#define G4    3072   // 4*H
#define DIN   4
#define HB    (HH * BATCH)

#define NB  148
#define NTC 512      // compute threads (warps 0-15)
#define NTP 256      // prep threads (warps 16-23)
#define NT  (NTC + NTP)
#define CPT 11       // cells per thread: h = hgrp + 74*k

// ---------------- scratch (static __device__, no allocs) ----------------
__device__ float  g_evsumtot[32];
__device__ float  g_hsumtot[32];
__device__ unsigned long long g_hx64[32];   // packed (flag<<32 | float bits) per step
__device__ float2 g_rb[TT * G4];            // (rowsum, bih+bhh) per row
__device__ float  g_gatesT[3 * HB];         // step-0 gates, TRANSPOSED [gate(i,g,o)][h][b]
__device__ unsigned g_bar_count;

__constant__ int c_g3row[3] = {0, 2, 3};    // live gates at t=0 (f dead: c0=0)
#define HXFLAG 0xF1A6ull

// ---------------- activations: HW tanh (MUFU.TANH) ----------------
__device__ __forceinline__ float htanh(float x) {
    float r; asm("tanh.approx.f32 %0, %1;" : "=f"(r) : "f"(x)); return r;
}
__device__ __forceinline__ float fsig(float x) {
    return fmaf(0.5f, htanh(0.5f * x), 0.5f);
}
__device__ __forceinline__ uint32_t to_tf32_bits(float x) {
    float r; asm("cvt.rna.tf32.f32 %0, %1;" : "=f"(r) : "f"(x));
    return __float_as_uint(r);
}
__device__ __forceinline__ float dot4(float4 x, float4 w) {
    return fmaf(x.x, w.x, fmaf(x.y, w.y, fmaf(x.z, w.z, x.w * w.w)));
}
#define BARC() asm volatile("bar.sync 1, %0;" :: "n"(NTC) : "memory")

// warp row-sum of 768 floats; result on lane 0
__device__ __forceinline__ float sum768(const float* __restrict__ p, int lane) {
    float4 a0 = *(const float4*)(p + 0 * 128 + lane * 4);
    float4 a1 = *(const float4*)(p + 1 * 128 + lane * 4);
    float4 a2 = *(const float4*)(p + 2 * 128 + lane * 4);
    float4 a3 = *(const float4*)(p + 3 * 128 + lane * 4);
    float4 a4 = *(const float4*)(p + 4 * 128 + lane * 4);
    float4 a5 = *(const float4*)(p + 5 * 128 + lane * 4);
    float s = ((a0.x + a0.y) + (a0.z + a0.w)) + ((a1.x + a1.y) + (a1.z + a1.w))
            + ((a2.x + a2.y) + (a2.z + a2.w)) + ((a3.x + a3.y) + (a3.z + a3.w))
            + ((a4.x + a4.y) + (a4.z + a4.w)) + ((a5.x + a5.y) + (a5.z + a5.w));
    #pragma unroll
    for (int o = 16; o; o >>= 1) s += __shfl_down_sync(0xffffffffu, s, o);
    return s;
}

// two row-sums with ALL 12 loads issued before any reduction (MLP 12)
__device__ __forceinline__ void sum768x2(const float* __restrict__ p0,
                                         const float* __restrict__ p1,
                                         int lane, float& s0out, float& s1out) {
    float4 a0 = *(const float4*)(p0 + 0 * 128 + lane * 4);
    float4 a1 = *(const float4*)(p0 + 1 * 128 + lane * 4);
    float4 a2 = *(const float4*)(p0 + 2 * 128 + lane * 4);
    float4 a3 = *(const float4*)(p0 + 3 * 128 + lane * 4);
    float4 a4 = *(const float4*)(p0 + 4 * 128 + lane * 4);
    float4 a5 = *(const float4*)(p0 + 5 * 128 + lane * 4);
    float4 b0 = *(const float4*)(p1 + 0 * 128 + lane * 4);
    float4 b1 = *(const float4*)(p1 + 1 * 128 + lane * 4);
    float4 b2 = *(const float4*)(p1 + 2 * 128 + lane * 4);
    float4 b3 = *(const float4*)(p1 + 3 * 128 + lane * 4);
    float4 b4 = *(const float4*)(p1 + 4 * 128 + lane * 4);
    float4 b5 = *(const float4*)(p1 + 5 * 128 + lane * 4);
    float s0 = ((a0.x + a0.y) + (a0.z + a0.w)) + ((a1.x + a1.y) + (a1.z + a1.w))
             + ((a2.x + a2.y) + (a2.z + a2.w)) + ((a3.x + a3.y) + (a3.z + a3.w))
             + ((a4.x + a4.y) + (a4.z + a4.w)) + ((a5.x + a5.y) + (a5.z + a5.w));
    float s1 = ((b0.x + b0.y) + (b0.z + b0.w)) + ((b1.x + b1.y) + (b1.z + b1.w))
             + ((b2.x + b2.y) + (b2.z + b2.w)) + ((b3.x + b3.y) + (b3.z + b3.w))
             + ((b4.x + b4.y) + (b4.z + b4.w)) + ((b5.x + b5.y) + (b5.z + b5.w));
    #pragma unroll
    for (int o = 16; o; o >>= 1) {
        s0 += __shfl_down_sync(0xffffffffu, s0, o);
        s1 += __shfl_down_sync(0xffffffffu, s1, o);
    }
    s0out = s0; s1out = s1;
}

// ---------------- init ----------------
__global__ void init_kernel(const float* __restrict__ fcb, float* __restrict__ out) {
    int t = blockIdx.x * blockDim.x + threadIdx.x;
    if (t < BATCH) out[t] = fcb[0];
    if (t < 32) { g_evsumtot[t] = 0.f; g_hsumtot[t] = 0.f; g_hx64[t] = 0ull; }
    if (t == 32) g_bar_count = 0;
}

// ---------------- front kernel: gemm0 (blocks 0..287) + prep step 1 (blocks 288..799) ----------------
#define BM 128
#define BN 64
#define BK 32
#define APAD 4
#define ASTR (BK + APAD)
#define NCH (HH / BK)
#define FB_GEMM 288
#define FB_TOTAL (FB_GEMM + 512)

__device__ __forceinline__ void mma_tf32(float* d, const uint32_t* a, const uint32_t* b) {
    asm volatile(
        "mma.sync.aligned.m16n8k8.row.col.f32.tf32.tf32.f32 "
        "{%0,%1,%2,%3}, {%4,%5,%6,%7}, {%8,%9}, {%0,%1,%2,%3};"
        : "+f"(d[0]), "+f"(d[1]), "+f"(d[2]), "+f"(d[3])
        : "r"(a[0]), "r"(a[1]), "r"(a[2]), "r"(a[3]), "r"(b[0]), "r"(b[1]));
}

__global__ __launch_bounds__(256) void front_kernel(
    const float* __restrict__ ev, const float* __restrict__ whh,
    const float* __restrict__ bih, const float* __restrict__ bhh) {
    __shared__ float As[BM * ASTR];
    __shared__ float Bs[BN * ASTR];
    const int blk = blockIdx.x;
    const int tid = threadIdx.x;
    const int wid = tid >> 5, lane = tid & 31;

    if (blk >= FB_GEMM) {
        // ---- prep for step 1 (high-parallelism sweep) ----
        const int w = (blk - FB_GEMM) * 8 + wid;      // 0..4095
        if (w < G4) {
            const int row = G4 + w;                    // t = 1 rows
            float s = sum768(whh + (size_t)row * HH, lane);
            if (lane == 0) g_rb[row] = make_float2(s, bih[row] + bhh[row]);
        } else {
            const int bb = w - G4;                     // 0..1023
            float s = sum768(ev + ((size_t)bb * TT + 1) * HH, lane);
            if (lane == 0) atomicAdd(&g_evsumtot[1], s);   // RED
        }
        return;
    }

    // ---- GEMM tile: 128(M batch) x 64(N) ----
    const int grp  = lane >> 2, tig = lane & 3;
    const int bx   = blk % 36, by = blk / 36;
    const int gidx = bx / 12;
    const int gate = c_g3row[gidx];
    const int hn   = (bx % 12) * BN;
    const int bm   = by * BM;
    const int wm   = (wid >> 1) * 32;     // 0..96
    const int wn   = (wid & 1) * 32;      // 0,32
    const size_t evStride = (size_t)TT * HH;

    float acc[2][4][4];
    #pragma unroll
    for (int i = 0; i < 2; i++)
        #pragma unroll
        for (int j = 0; j < 4; j++)
            #pragma unroll
            for (int r = 0; r < 4; r++) acc[i][j][r] = 0.f;

    float4 ra[6];
    #pragma unroll
    for (int i = 0; i < 6; i++) {
        const int lin = tid + i * 256;
        const int r = lin >> 3, q = (lin & 7) * 4;
        ra[i] = (r < BM)
            ? *(const float4*)(ev + (size_t)(bm + r) * evStride + q)
            : *(const float4*)(whh + (size_t)(gate * HH + hn + (r - BM)) * HH + q);
    }

    for (int chunk = 0; chunk < NCH; chunk++) {
        #pragma unroll
        for (int i = 0; i < 6; i++) {
            const int lin = tid + i * 256;
            const int r = lin >> 3, q = (lin & 7) * 4;
            uint4 t4; t4.x = to_tf32_bits(ra[i].x); t4.y = to_tf32_bits(ra[i].y);
                      t4.z = to_tf32_bits(ra[i].z); t4.w = to_tf32_bits(ra[i].w);
            if (r < BM) *(uint4*)(As + r * ASTR + q) = t4;
            else        *(uint4*)(Bs + (r - BM) * ASTR + q) = t4;
        }
        __syncthreads();
        if (chunk + 1 < NCH) {
            const int k0 = (chunk + 1) * BK;
            #pragma unroll
            for (int i = 0; i < 6; i++) {
                const int lin = tid + i * 256;
                const int r = lin >> 3, q = (lin & 7) * 4;
                ra[i] = (r < BM)
                    ? *(const float4*)(ev + (size_t)(bm + r) * evStride + k0 + q)
                    : *(const float4*)(whh + (size_t)(gate * HH + hn + (r - BM)) * HH + k0 + q);
            }
        }
        #pragma unroll
        for (int kk = 0; kk < 4; kk++) {
            const int k8 = kk * 8;
            uint32_t af[2][4];
            #pragma unroll
            for (int mi = 0; mi < 2; mi++) {
                const float* ar = As + (wm + mi * 16) * ASTR + k8;
                af[mi][0] = __float_as_uint(ar[grp * ASTR + tig]);
                af[mi][1] = __float_as_uint(ar[(grp + 8) * ASTR + tig]);
                af[mi][2] = __float_as_uint(ar[grp * ASTR + tig + 4]);
                af[mi][3] = __float_as_uint(ar[(grp + 8) * ASTR + tig + 4]);
            }
            #pragma unroll
            for (int ni = 0; ni < 4; ni++) {
                const float* br = Bs + (wn + ni * 8 + grp) * ASTR + k8;
                uint32_t bf[2];
                bf[0] = __float_as_uint(br[tig]);
                bf[1] = __float_as_uint(br[tig + 4]);
                #pragma unroll
                for (int mi = 0; mi < 2; mi++)
                    mma_tf32(acc[mi][ni], af[mi], bf);
            }
        }
        __syncthreads();
    }

    float* gT = g_gatesT + (size_t)gidx * HB;
    #pragma unroll
    for (int mi = 0; mi < 2; mi++) {
        const int m0 = bm + wm + mi * 16 + grp;
        #pragma unroll
        for (int ni = 0; ni < 4; ni++) {
            const int h0 = hn + wn + ni * 8 + 2 * tig;
            gT[(size_t)h0 * BATCH + m0]           = acc[mi][ni][0];
            gT[(size_t)(h0 + 1) * BATCH + m0]     = acc[mi][ni][1];
            gT[(size_t)h0 * BATCH + m0 + 8]       = acc[mi][ni][2];
            gT[(size_t)(h0 + 1) * BATCH + m0 + 8] = acc[mi][ni][3];
        }
    }
}

// ---------------- prep-warp work for one step (8 warps, window-locked) ----------------
__device__ __forceinline__ void prep_step(int tp, int blk, int pw, int plane,
                                          const float* __restrict__ whh,
                                          const float* __restrict__ ev,
                                          const float* __restrict__ bih,
                                          const float* __restrict__ bhh) {
    // round 1: rows j = pw and pw+8 (always valid)
    {
        const int r0 = blk + 148 * pw;
        const int r1 = blk + 148 * (pw + 8);
        const int row0 = tp * G4 + r0, row1 = tp * G4 + r1;
        float s0, s1;
        sum768x2(whh + (size_t)row0 * HH, whh + (size_t)row1 * HH, plane, s0, s1);
        if (plane == 0) {
            g_rb[row0] = make_float2(s0, bih[row0] + bhh[row0]);
            g_rb[row1] = make_float2(s1, bih[row1] + bhh[row1]);
        }
    }
    // round 2: row j = pw+16 (maybe) + ev batch blk*7+pw (maybe)
    {
        const int j2 = pw + 16;
        const int r2 = blk + 148 * j2;
        const bool v2 = (j2 < 21) && (r2 < G4);
        const int bb = blk * 7 + pw;
        const bool ve = (pw < 7) && (bb < BATCH);
        const int row2 = tp * G4 + (v2 ? r2 : 0);
        const float* p2 = whh + (size_t)row2 * HH;
        const float* pe = ve ? (ev + ((size_t)bb * TT + tp) * HH) : (ev);
        float s2, se;
        sum768x2(p2, pe, plane, s2, se);
        if (plane == 0) {
            if (v2) g_rb[row2] = make_float2(s2, bih[row2] + bhh[row2]);
            if (ve) atomicAdd(&g_evsumtot[tp], se);   // RED
        }
    }
    if (plane == 0) __threadfence();
}

// ---------------- persistent sequential kernel: windows 0..19 + fc ----------------
__global__ __launch_bounds__(NT, 1) void seq_kernel(
    const float* __restrict__ price, const float* __restrict__ ev,
    const float* __restrict__ whh,   const float* __restrict__ wih,
    const float* __restrict__ bih,   const float* __restrict__ bhh,
    const float* __restrict__ fcw,   float* __restrict__ out) {
    __shared__ float4 s_w[2][4 * CPT];
    __shared__ float  s_gc[4 * CPT];
    __shared__ float  s_red[16];
    __shared__ float  s_hx;
    __shared__ float  s_fcw[CPT];

    const int blk = blockIdx.x;
    const int tix = threadIdx.x;
    const int lane = tix & 31, wrp = tix >> 5;
    const int hgrp = blk >> 1;                   // uniform per block (0..73)

    if (tix < NTC) {
        // ======================= COMPUTE WARPS (0-15) =======================
        const int b = ((blk & 1) << 9) + tix;    // constant per thread
        float c[CPT];
        float2 rbreg = make_float2(0.f, 0.f);
        float4 wreg  = make_float4(0.f, 0.f, 0.f, 0.f);

        // ---- window 0: cells t=0 from gemm gates ----
        if (tix < 3 * CPT) {
            const int g = tix / CPT, k = tix - g * CPT;
            const int h = hgrp + 74 * k;
            if (h < HH) {
                const int row = c_g3row[g] * HH + h;
                s_gc[g * CPT + k] = bih[row] + bhh[row];
                s_w[0][g * CPT + k] = *(const float4*)(wih + (size_t)row * DIN);
            }
        }
        BARC();
        if (tix < 4 * CPT) {                     // prefetch step-1 consts (sealed by front)
            const int g = tix / CPT, k = tix - g * CPT;
            const int h = hgrp + 74 * k;
            if (h < HH) {
                const int row = G4 + g * HH + h;
                rbreg = g_rb[row];
                wreg  = *(const float4*)(wih + (size_t)row * DIN);
            }
        }
        {
            float4 x = *(const float4*)(price + (size_t)b * TT * DIN);
            float hloc = 0.f;
            #pragma unroll
            for (int k = 0; k < CPT; k++) {
                const int h = hgrp + 74 * k;
                if (h < HH) {
                    const size_t base = ((size_t)h << 10) + b;
                    float gi = g_gatesT[base]          + dot4(x, s_w[0][k])           + s_gc[k];
                    float gg = g_gatesT[HB + base]     + dot4(x, s_w[0][CPT + k])     + s_gc[CPT + k];
                    float go = g_gatesT[2 * HB + base] + dot4(x, s_w[0][2 * CPT + k]) + s_gc[2 * CPT + k];
                    float cv = fsig(gi) * htanh(gg);
                    c[k] = cv;
                    hloc += fsig(go) * htanh(cv);
                } else c[k] = 0.f;
            }
            if (tix < 4 * CPT) s_w[1][tix] = wreg;
            #pragma unroll
            for (int o = 16; o; o >>= 1) hloc += __shfl_down_sync(0xffffffffu, hloc, o);
            if (lane == 0) s_red[wrp] = hloc;
        }
        __syncthreads();                          // JOINT W0
        if (tix == 0) {
            float v = 0.f;
            #pragma unroll
            for (int q = 0; q < 16; q++) v += s_red[q];
            atomicAdd(&g_hsumtot[0], v);          // RED
            __threadfence();
            unsigned arr = atomicAdd(&g_bar_count, 1u);
            if (arr == (unsigned)NB - 1) {        // last arriver publishes hx[1]
                float hx = ((volatile float*)g_hsumtot)[0]
                         + ((volatile float*)g_evsumtot)[1];
                *(volatile unsigned long long*)&g_hx64[1] =
                    (HXFLAG << 32) | (unsigned long long)__float_as_uint(hx);
            }
        }

        // ---- windows t = 1..19 ----
        for (int t = 1; t < TT; t++) {
            const int cur = t & 1;
            if (tix == 0) {                       // single packed poll = barrier + hx
                volatile unsigned long long* p = &g_hx64[t];
                unsigned long long v;
                do { v = *p; } while ((v >> 32) != HXFLAG);
                s_hx = __uint_as_float((unsigned)(v & 0xFFFFFFFFull));
            }
            BARC();
            if (tix < 4 * CPT) s_gc[tix] = fmaf(s_hx, rbreg.x, rbreg.y);
            BARC();
            // prefetch step t+1 consts (sealed by the barrier just polled)
            if (t < TT - 1 && tix < 4 * CPT) {
                const int g = tix / CPT, k = tix - g * CPT;
                const int h = hgrp + 74 * k;
                if (h < HH) {
                    const int row = (t + 1) * G4 + g * HH + h;
                    rbreg = g_rb[row];
                    wreg  = *(const float4*)(wih + (size_t)row * DIN);
                }
            }
            if (t == TT - 2 && tix >= 4 * CPT && tix < 5 * CPT) {
                const int k = tix - 4 * CPT;
                const int h = hgrp + 74 * k;
                s_fcw[k] = (h < HH) ? fcw[h] : 0.f;
            }

            float4 x = *(const float4*)(price + ((size_t)b * TT + t) * DIN);
            float hloc = 0.f, floc = 0.f;
            #pragma unroll
            for (int k = 0; k < CPT; k++) {
                const int h = hgrp + 74 * k;
                if (h < HH) {
                    float gi = dot4(x, s_w[cur][k])           + s_gc[k];
                    float gf = dot4(x, s_w[cur][CPT + k])     + s_gc[CPT + k];
                    float gg = dot4(x, s_w[cur][2 * CPT + k]) + s_gc[2 * CPT + k];
                    float go = dot4(x, s_w[cur][3 * CPT + k]) + s_gc[3 * CPT + k];
                    float ct = fsig(gf) * c[k] + fsig(gi) * htanh(gg);
                    c[k] = ct;
                    float hv = fsig(go) * htanh(ct);
                    if (t == TT - 1) floc = fmaf(hv, s_fcw[k], floc);
                    else             hloc += hv;
                }
            }
            if (t < TT - 1 && tix < 4 * CPT) s_w[cur ^ 1][tix] = wreg;

            if (t == TT - 1) {
                atomicAdd(&out[b], floc);         // RED, 74 per address
            } else {
                #pragma unroll
                for (int o = 16; o; o >>= 1) hloc += __shfl_down_sync(0xffffffffu, hloc, o);
                if (lane == 0) s_red[wrp] = hloc;
                __syncthreads();                  // JOINT W(t)
                if (tix == 0) {
                    float v = 0.f;
                    #pragma unroll
                    for (int q = 0; q < 16; q++) v += s_red[q];
                    atomicAdd(&g_hsumtot[t], v);  // RED
                    __threadfence();
                    unsigned arr = atomicAdd(&g_bar_count, 1u);
                    if (arr == (unsigned)(t + 1) * NB - 1) {
                        float hx = ((volatile float*)g_hsumtot)[t]
                                 + ((volatile float*)g_evsumtot)[t + 1];
                        *(volatile unsigned long long*)&g_hx64[t + 1] =
                            (HXFLAG << 32) | (unsigned long long)__float_as_uint(hx);
                    }
                }
            }
        }
    } else {
        // ================= PREP WARPS (16-23): WINDOW-LOCKED =================
        const int ptix = tix - NTC;
        const int pw = ptix >> 5, plane = ptix & 31;
        for (int w = 0; w < 19; w++) {            // match compute's 19 joint syncs
            if (w <= 17) prep_step(w + 2, blk, pw, plane, whh, ev, bih, bhh);
            __syncthreads();                      // JOINT W(w)
        }
    }
}

// ---------------- launch ----------------
extern "C" void kernel_launch(void* const* d_in, const int* in_sizes, int n_in,
                              void* d_out, int out_size) {
    const float* price = (const float*)d_in[0];   // (B,T,4)
    const float* ev    = (const float*)d_in[1];   // (B,T,H)
    const float* wih   = (const float*)d_in[2];   // (T,4H,4)
    const float* whh   = (const float*)d_in[3];   // (T,4H,H)
    const float* bih   = (const float*)d_in[4];   // (T,4H)
    const float* bhh   = (const float*)d_in[5];   // (T,4H)
    const float* fcw   = (const float*)d_in[6];   // (1,H)
    const float* fcb   = (const float*)d_in[7];   // (1,)
    float* out = (float*)d_out;                    // (B,1)
    (void)in_sizes; (void)n_in; (void)out_size;

    init_kernel<<<4, 256>>>(fcb, out);
    front_kernel<<<FB_TOTAL, 256>>>(ev, whh, bih, bhh);
    seq_kernel<<<NB, NT>>>(price, ev, whh, wih, bih, bhh, fcw, out);
}